// round 15
// baseline (speedup 1.0000x reference)
#include <cuda_runtime.h>
#include <cuda_fp16.h>
#include <cstdint>

#define BSZ 32
#define NP  64
#define NN  (NP*NP)   // 4096

typedef unsigned long long u64;

// ---------------- device scratch ----------------
__device__ float g_att[6 * BSZ * NN];     // attq1, attq2, attq3, Tjk, Tjl, Akl (pre-scaled 0.0625)
__device__ float g_anchor2[2 * BSZ * NP]; // per (k-half, b, i): 256 * Sum tanh(z)*det16^2
__device__ float g_det2[BSZ * NP];        // per (b, i): Sum det^2 (exact, f32 analytic)

// ---------------- f32x2 packed helpers (prep/cross only) ----------------
__device__ __forceinline__ u64 pk2(float lo, float hi) {
    u64 r; asm("mov.b64 %0,{%1,%2};" : "=l"(r) : "f"(lo), "f"(hi)); return r;
}
__device__ __forceinline__ void upk2(float& lo, float& hi, u64 v) {
    asm("mov.b64 {%0,%1},%2;" : "=f"(lo), "=f"(hi) : "l"(v));
}
__device__ __forceinline__ u64 dup2(float x) { return pk2(x, x); }
__device__ __forceinline__ u64 mul2(u64 a, u64 b) {
    u64 r; asm("mul.rn.f32x2 %0,%1,%2;" : "=l"(r) : "l"(a), "l"(b)); return r;
}
__device__ __forceinline__ u64 fma2(u64 a, u64 b, u64 c) {
    u64 r; asm("fma.rn.f32x2 %0,%1,%2,%3;" : "=l"(r) : "l"(a), "l"(b), "l"(c)); return r;
}

// ---------------- f16x2 helpers ----------------
__device__ __forceinline__ __half2 mkh2(float lo, float hi) {
    uint32_t r; asm("cvt.rn.f16x2.f32 %0,%1,%2;" : "=r"(r) : "f"(hi), "f"(lo));
    return *reinterpret_cast<__half2*>(&r);
}
__device__ __forceinline__ __half2 h2_from_f32x2(u64 v) {
    float lo, hi; upk2(lo, hi, v); return mkh2(lo, hi);
}
__device__ __forceinline__ __half2 tanh_h2(__half2 x) {
    uint32_t w = *reinterpret_cast<uint32_t*>(&x);
    asm("tanh.approx.f16x2 %0,%1;" : "=r"(w) : "r"(w));
    return *reinterpret_cast<__half2*>(&w);
}
__device__ __forceinline__ __half2 u2h2(uint32_t w) { return *reinterpret_cast<__half2*>(&w); }
__device__ __forceinline__ uint32_t h22u(__half2 h) { return *reinterpret_cast<uint32_t*>(&h); }
// signed f16 -> f32 widen, pure ALU (shift/mask/add).
__device__ __forceinline__ void widen_h2(uint32_t w, float& flo, float& fhi) {
    uint32_t mlo = ((w << 13) & 0x0FFFE000u) + 0x38000000u;
    flo = __uint_as_float(mlo | ((w << 16) & 0x80000000u));
    uint32_t mhi = ((w >> 3) & 0x0FFFE000u) + 0x38000000u;
    fhi = __uint_as_float(mhi | (w & 0x80000000u));
}

// ---------------- k12: fused dense + six N x N attention matrices ----------------
// out[r*64+c] = 0.0625 * dot(S1[c,:], S2[r,:])
// m0: attq1[i][j] (S1=K1,S2=Q)   m3: Tjk[k][j] (S1=K1,S2=K2)
// m1: attq2[i][k] (S1=K2,S2=Q)   m4: Tjl[l][j] (S1=K1,S2=K3)
// m2: attq3[i][l] (S1=K3,S2=Q)   m5: Akl[k][l] (S1=K3,S2=K2)
__global__ void k12_att(const float* __restrict__ pts,
                        const float* __restrict__ Wq,  const float* __restrict__ bq,
                        const float* __restrict__ Wk1, const float* __restrict__ bk1,
                        const float* __restrict__ Wk2, const float* __restrict__ bk2,
                        const float* __restrict__ Wk3, const float* __restrict__ bk3) {
    __shared__ float S1t[64 * 65];
    __shared__ float S2s[64 * 64];
    int blk = blockIdx.x;
    int b = blk / 6, m = blk % 6;
    const int s1tab[6] = {1, 2, 3, 1, 1, 3};
    const int s2tab[6] = {0, 0, 0, 2, 3, 2};
    int s1 = s1tab[m], s2 = s2tab[m];
    const float* WA; const float* bA;
    const float* WB; const float* bB;
    if      (s1 == 1) { WA = Wk1; bA = bk1; }
    else if (s1 == 2) { WA = Wk2; bA = bk2; }
    else              { WA = Wk3; bA = bk3; }
    if      (s2 == 0) { WB = Wq;  bB = bq;  }
    else if (s2 == 2) { WB = Wk2; bB = bk2; }
    else              { WB = Wk3; bB = bk3; }
    for (int t = threadIdx.x; t < NN; t += blockDim.x) {
        int n = t >> 6, d = t & 63;
        const float* p = pts + (b * NP + n) * 3;
        float v1 = fmaf(p[0], WA[d], fmaf(p[1], WA[64 + d], fmaf(p[2], WA[128 + d], bA[d])));
        float v2 = fmaf(p[0], WB[d], fmaf(p[1], WB[64 + d], fmaf(p[2], WB[128 + d], bB[d])));
        S1t[d * 65 + n] = v1;
        S2s[n * 64 + d] = v2;
    }
    __syncthreads();
    const float cscale = 0.0625f;
    for (int e = threadIdx.x; e < NN; e += blockDim.x) {
        int r = e >> 6, c = e & 63;
        float acc = 0.f;
        #pragma unroll
        for (int d = 0; d < 64; d++)
            acc = fmaf(S1t[d * 65 + c], S2s[r * 64 + d], acc);
        g_att[(m * BSZ + b) * NN + e] = acc * cscale;
    }
}

// ---------------- k3b: analytic Sum_jkl det^2 per (b,i), exact f32 ----------------
__global__ void k3b_det2(const float* __restrict__ pts) {
    __shared__ float DX[64], DY[64], DZ[64];
    __shared__ float red2_s[2];
    int bx = blockIdx.x;
    int b = bx >> 6, i = bx & 63;
    int t = threadIdx.x, lane = t & 31, warp = t >> 5;
    const float* pi = pts + (b * 64 + i) * 3;
    const float* pt = pts + (b * 64 + t) * 3;
    float ax = pt[0] - pi[0], ay = pt[1] - pi[1], az = pt[2] - pi[2];
    DX[t] = ax; DY[t] = ay; DZ[t] = az;
    __syncthreads();
    float mxx = 0, mxy = 0, mxz = 0, myy = 0, myz = 0, mzz = 0;
    #pragma unroll 8
    for (int j = 0; j < 64; j++) {
        float x = DX[j], y = DY[j], z = DZ[j];
        mxx = fmaf(x, x, mxx); mxy = fmaf(x, y, mxy); mxz = fmaf(x, z, mxz);
        myy = fmaf(y, y, myy); myz = fmaf(y, z, myz); mzz = fmaf(z, z, mzz);
    }
    float q = 0.f;
    #pragma unroll 8
    for (int l = 0; l < 64; l++) {
        float lx = DX[l], ly = DY[l], lz = DZ[l];
        float vx = ay * lz - az * ly;
        float vy = az * lx - ax * lz;
        float vz = ax * ly - ay * lx;
        float f = mxx * vx * vx + myy * vy * vy + mzz * vz * vz
                + 2.f * (mxy * vx * vy + mxz * vx * vz + myz * vy * vz);
        q += f;
    }
    #pragma unroll
    for (int o = 16; o; o >>= 1) q += __shfl_down_sync(0xffffffffu, q, o);
    if (lane == 0) red2_s[warp] = q;
    __syncthreads();
    if (t == 0) g_det2[b * 64 + i] = red2_s[0] + red2_s[1];
}

// ---------------- pad: k3 must be the 4th launch (ncu capture slot) ----------------
__global__ void k_pad() {}

// ---------------- k3: 537M-eval tanh-gated det core, all-f16x2 math ----------------
// grid 4096 = B(32) x anchors(64) x k-halves(2); block 128 (4 warps).
// Warp owns 8 k's; per t4-iter each lane handles k_a and k_b=k_a+4,
// with the (l=lane, l+32) pair packed in the two f16 halves -> 4 evals/lane/j.
// Per-iter LDS: 1x LDS.128 (J) + 1x LDS.64 (paired Ta,Tb) + 1x LDS.32 (P).
__global__ void __launch_bounds__(128, 9) k3_core(const float* __restrict__ pts) {
    __shared__ uint4    JH4_s[64];       // (jx2h, jy2h, jz2h, 0) one LDS.128 bcast  1KB
    __shared__ uint2    TT_s[16 * 64];   // [(w*4+t4)*64+j] = ((tka,tka),(tkb,tkb))  8KB
    __shared__ uint32_t P2_s[64 * 32];   // [j*32+lane] = f16x2(P(l,j), P(l+32,j))  8KB
    __shared__ float4   D4_s[64];        // raw f32 disp  1KB
    __shared__ float    red_s[4];

    int bx = blockIdx.x;
    int h  = bx & 1;
    int i  = (bx >> 1) & 63;
    int b  = bx >> 7;
    int k0 = h * 32;
    int tid = threadIdx.x, warp = tid >> 5, lane = tid & 31;

    const float* attq1 = g_att + (0 * BSZ + b) * NN;
    const float* attq2 = g_att + (1 * BSZ + b) * NN;
    const float* attq3 = g_att + (2 * BSZ + b) * NN;
    const float* Tjk   = g_att + (3 * BSZ + b) * NN;
    const float* Tjl   = g_att + (4 * BSZ + b) * NN;
    const float* Akl   = g_att + (5 * BSZ + b) * NN;

    // ---- prep ----
    {
        const float* pi = pts + (b * NP + i) * 3;
        float pix = pi[0], piy = pi[1], piz = pi[2];
        if (tid < 64) {
            const float* pp = pts + (b * NP + tid) * 3;
            float dx = pp[0] - pix, dy = pp[1] - piy, dz = pp[2] - piz;
            D4_s[tid] = make_float4(dx, dy, dz, 0.f);
            uint4 v;
            v.x = h22u(mkh2(dx, dx));
            v.y = h22u(mkh2(dy, dy));
            v.z = h22u(mkh2(dz, dz));
            v.w = 0u;
            JH4_s[tid] = v;
        }
    }
    for (int idx = tid; idx < 1024; idx += 128) {       // paired pre-dup'd Tjk
        int w = idx >> 8, r = idx & 255;
        int t = r >> 6,   j = r & 63;
        int ka = k0 + 8 * w + t;
        float va = Tjk[ka * 64 + j];
        float vb = Tjk[(ka + 4) * 64 + j];
        uint2 tt;
        tt.x = h22u(mkh2(va, va));
        tt.y = h22u(mkh2(vb, vb));
        TT_s[idx] = tt;
    }
    for (int t = tid; t < 2048; t += 128) {             // fused P f16x2 pairs
        int lp = t & 31, j = t >> 5;
        float a1j = attq1[i * 64 + j];
        float lo = Tjl[lp * 64 + j]        + a1j + attq3[i * 64 + lp];
        float hi = Tjl[(lp + 32) * 64 + j] + a1j + attq3[i * 64 + lp + 32];
        P2_s[j * 32 + lp] = h22u(mkh2(lo, hi));
    }
    __syncthreads();

    // per-lane packed dl for (l=lane, l+32), pre-scaled by 1/16 (det scale)
    float4 da = D4_s[lane], db = D4_s[lane + 32];
    u64 sc = dup2(0.0625f);
    u64 dlx2 = mul2(pk2(da.x, db.x), sc);
    u64 dly2 = mul2(pk2(da.y, db.y), sc);
    u64 dlz2 = mul2(pk2(da.z, db.z), sc);
    float accA = 0.f, accB = 0.f;

    #pragma unroll 1
    for (int t4 = 0; t4 < 4; t4++) {
        int ka = k0 + 8 * warp + t4;             // uniform within warp
        int kb = ka + 4;
        float4 dka = D4_s[ka];
        float4 dkb = D4_s[kb];
        float aika = __ldg(attq2 + i * 64 + ka);
        float aikb = __ldg(attq2 + i * 64 + kb);
        __half2 base_ha = mkh2(aika + __ldg(Akl + ka * 64 + lane),
                               aika + __ldg(Akl + ka * 64 + lane + 32));
        __half2 base_hb = mkh2(aikb + __ldg(Akl + kb * 64 + lane),
                               aikb + __ldg(Akl + kb * 64 + lane + 32));
        // cross(dk, dl/16) in f32x2, then pack to f16x2 (hoisted)
        __half2 cxa = h2_from_f32x2(fma2(dup2(dka.y), dlz2, mul2(dup2(-dka.z), dly2)));
        __half2 cya = h2_from_f32x2(fma2(dup2(dka.z), dlx2, mul2(dup2(-dka.x), dlz2)));
        __half2 cza = h2_from_f32x2(fma2(dup2(dka.x), dly2, mul2(dup2(-dka.y), dlx2)));
        __half2 cxb = h2_from_f32x2(fma2(dup2(dkb.y), dlz2, mul2(dup2(-dkb.z), dly2)));
        __half2 cyb = h2_from_f32x2(fma2(dup2(dkb.z), dlx2, mul2(dup2(-dkb.x), dlz2)));
        __half2 czb = h2_from_f32x2(fma2(dup2(dkb.x), dly2, mul2(dup2(-dkb.y), dlx2)));
        const uint2* TRow = TT_s + (warp * 4 + t4) * 64;

        #pragma unroll 1
        for (int j16 = 0; j16 < 4; j16++) {     // 16-j f16 windows
            __half2 winA = u2h2(0u), winB = u2h2(0u);
            #pragma unroll
            for (int jj = 0; jj < 16; jj++) {
                int j = j16 * 16 + jj;
                uint4 jv = JH4_s[j];                         // LDS.128 bcast
                __half2 jx = u2h2(jv.x), jy = u2h2(jv.y), jz = u2h2(jv.z);
                uint2 tt = TRow[j];                          // LDS.64 bcast (Ta,Tb)
                __half2 ta = u2h2(tt.x), tb = u2h2(tt.y);
                __half2 p  = u2h2(P2_s[j * 32 + lane]);      // LDS.32 per-lane
                __half2 ea = __hadd2(__hadd2(p, ta), base_ha);
                __half2 eb = __hadd2(__hadd2(p, tb), base_hb);
                __half2 tha = tanh_h2(ea);                   // 1 XU per 2 evals
                __half2 thb = tanh_h2(eb);
                __half2 deta = __hfma2(jx, cxa, __hfma2(jy, cya, __hmul2(jz, cza)));
                __half2 detb = __hfma2(jx, cxb, __hfma2(jy, cyb, __hmul2(jz, czb)));
                winA = __hfma2(__hmul2(deta, deta), tha, winA);
                winB = __hfma2(__hmul2(detb, detb), thb, winB);
            }
            float l0, h0, l1, h1;
            widen_h2(h22u(winA), l0, h0);                    // ALU-only widen
            widen_h2(h22u(winB), l1, h1);
            accA += (l0 + h0);
            accB += (l1 + h1);
        }
    }

    // ---- reduction ----
    float acc = (accA + accB) * 256.f;          // undo det/16 scaling
    #pragma unroll
    for (int o = 16; o; o >>= 1) acc += __shfl_down_sync(0xffffffffu, acc, o);
    if (lane == 0) red_s[warp] = acc;
    __syncthreads();
    if (tid == 0) {
        float s = red_s[0] + red_s[1] + red_s[2] + red_s[3];
        g_anchor2[h * BSZ * NP + b * NP + i] = s;
    }
}

// ---------------- k4: pooled -> gelu MLP head (warp per batch) ----------------
// anchor_i = 0.5*(Sum det^2 + Sum tanh*det^2); pooled = Sum_i anchor_i / N^4
__global__ void k4_head(const float* __restrict__ W1, const float* __restrict__ b1,
                        const float* __restrict__ W2, const float* __restrict__ b2,
                        float* __restrict__ out) {
    int warp = threadIdx.x >> 5, lane = threadIdx.x & 31;
    int b = warp;
    float s = g_anchor2[b * 64 + lane] + g_anchor2[b * 64 + lane + 32]
            + g_anchor2[BSZ * NP + b * 64 + lane] + g_anchor2[BSZ * NP + b * 64 + lane + 32]
            + g_det2[b * 64 + lane] + g_det2[b * 64 + lane + 32];
    #pragma unroll
    for (int o = 16; o; o >>= 1) s += __shfl_xor_sync(0xffffffffu, s, o);
    float pooled = s * (0.5f / 16777216.f);        // 0.5 gate split, / (N^3 * N)
    float x  = fmaf(pooled, W1[lane], b1[lane]);   // lane = hidden unit
    float x3 = x * x * x;
    float t  = tanhf(0.7978845608028654f * fmaf(0.044715f, x3, x));
    float hc = 0.5f * x * (1.f + t);               // tanh-approx gelu
    float y  = hc * W2[lane];
    #pragma unroll
    for (int o = 16; o; o >>= 1) y += __shfl_xor_sync(0xffffffffu, y, o);
    if (lane == 0) out[b] = y + b2[0];
}

// ---------------- launch ----------------
extern "C" void kernel_launch(void* const* d_in, const int* in_sizes, int n_in,
                              void* d_out, int out_size) {
    const float* pts = (const float*)d_in[0];
    const float* Wq  = (const float*)d_in[1];
    const float* bq  = (const float*)d_in[2];
    const float* Wk1 = (const float*)d_in[3];
    const float* bk1 = (const float*)d_in[4];
    const float* Wk2 = (const float*)d_in[5];
    const float* bk2 = (const float*)d_in[6];
    const float* Wk3 = (const float*)d_in[7];
    const float* bk3 = (const float*)d_in[8];
    const float* W1  = (const float*)d_in[9];
    const float* b1  = (const float*)d_in[10];
    const float* W2  = (const float*)d_in[11];
    const float* b2  = (const float*)d_in[12];
    float* out = (float*)d_out;

    k12_att<<<BSZ * 6, 256>>>(pts, Wq, bq, Wk1, bk1, Wk2, bk2, Wk3, bk3);
    k3b_det2<<<BSZ * NP, 64>>>(pts);
    k_pad<<<1, 32>>>();                       // k3 = 4th launch -> ncu capture slot
    k3_core<<<BSZ * NP * 2, 128>>>(pts);
    k4_head<<<1, BSZ * 32>>>(W1, b1, W2, b2, out);
}

// round 17
// speedup vs baseline: 1.7088x; 1.7088x over previous
#include <cuda_runtime.h>
#include <cuda_fp16.h>
#include <cstdint>

#define BSZ 32
#define NP  64
#define NN  (NP*NP)   // 4096

typedef unsigned long long u64;

// ---------------- device scratch ----------------
__device__ float g_att[6 * BSZ * NN];     // attq1, attq2, attq3, Tjk, Tjl, Akl (pre-scaled 0.0625)
__device__ float g_anchor2[2 * BSZ * NP]; // per (k-half, b, i): 256 * Sum tanh(z)*det16^2
__device__ float g_det2[BSZ * NP];        // per (b, i): Sum det^2 (exact, f32 analytic)

// ---------------- f32x2 packed helpers (prep/cross only) ----------------
__device__ __forceinline__ u64 pk2(float lo, float hi) {
    u64 r; asm("mov.b64 %0,{%1,%2};" : "=l"(r) : "f"(lo), "f"(hi)); return r;
}
__device__ __forceinline__ void upk2(float& lo, float& hi, u64 v) {
    asm("mov.b64 {%0,%1},%2;" : "=f"(lo), "=f"(hi) : "l"(v));
}
__device__ __forceinline__ u64 dup2(float x) { return pk2(x, x); }
__device__ __forceinline__ u64 mul2(u64 a, u64 b) {
    u64 r; asm("mul.rn.f32x2 %0,%1,%2;" : "=l"(r) : "l"(a), "l"(b)); return r;
}
__device__ __forceinline__ u64 fma2(u64 a, u64 b, u64 c) {
    u64 r; asm("fma.rn.f32x2 %0,%1,%2,%3;" : "=l"(r) : "l"(a), "l"(b), "l"(c)); return r;
}

// ---------------- f16x2 helpers ----------------
__device__ __forceinline__ __half2 mkh2(float lo, float hi) {
    uint32_t r; asm("cvt.rn.f16x2.f32 %0,%1,%2;" : "=r"(r) : "f"(hi), "f"(lo));
    return *reinterpret_cast<__half2*>(&r);
}
__device__ __forceinline__ __half2 h2_from_f32x2(u64 v) {
    float lo, hi; upk2(lo, hi, v); return mkh2(lo, hi);
}
__device__ __forceinline__ __half2 tanh_h2(__half2 x) {
    uint32_t w = *reinterpret_cast<uint32_t*>(&x);
    asm("tanh.approx.f16x2 %0,%1;" : "=r"(w) : "r"(w));
    return *reinterpret_cast<__half2*>(&w);
}
__device__ __forceinline__ __half2 u2h2(uint32_t w) { return *reinterpret_cast<__half2*>(&w); }
__device__ __forceinline__ uint32_t h22u(__half2 h) { return *reinterpret_cast<uint32_t*>(&h); }
// signed f16 -> f32 widen, pure ALU (shift/mask/add).
__device__ __forceinline__ void widen_h2(uint32_t w, float& flo, float& fhi) {
    uint32_t mlo = ((w << 13) & 0x0FFFE000u) + 0x38000000u;
    flo = __uint_as_float(mlo | ((w << 16) & 0x80000000u));
    uint32_t mhi = ((w >> 3) & 0x0FFFE000u) + 0x38000000u;
    fhi = __uint_as_float(mhi | (w & 0x80000000u));
}

// ---------------- k12: fused dense + six N x N attention matrices ----------------
// out[r*64+c] = 0.0625 * dot(S1[c,:], S2[r,:])
// m0: attq1[i][j] (S1=K1,S2=Q)   m3: Tjk[k][j] (S1=K1,S2=K2)
// m1: attq2[i][k] (S1=K2,S2=Q)   m4: Tjl[l][j] (S1=K1,S2=K3)
// m2: attq3[i][l] (S1=K3,S2=Q)   m5: Akl[k][l] (S1=K3,S2=K2)
__global__ void k12_att(const float* __restrict__ pts,
                        const float* __restrict__ Wq,  const float* __restrict__ bq,
                        const float* __restrict__ Wk1, const float* __restrict__ bk1,
                        const float* __restrict__ Wk2, const float* __restrict__ bk2,
                        const float* __restrict__ Wk3, const float* __restrict__ bk3) {
    __shared__ float S1t[64 * 65];
    __shared__ float S2s[64 * 64];
    int blk = blockIdx.x;
    int b = blk / 6, m = blk % 6;
    const int s1tab[6] = {1, 2, 3, 1, 1, 3};
    const int s2tab[6] = {0, 0, 0, 2, 3, 2};
    int s1 = s1tab[m], s2 = s2tab[m];
    const float* WA; const float* bA;
    const float* WB; const float* bB;
    if      (s1 == 1) { WA = Wk1; bA = bk1; }
    else if (s1 == 2) { WA = Wk2; bA = bk2; }
    else              { WA = Wk3; bA = bk3; }
    if      (s2 == 0) { WB = Wq;  bB = bq;  }
    else if (s2 == 2) { WB = Wk2; bB = bk2; }
    else              { WB = Wk3; bB = bk3; }
    for (int t = threadIdx.x; t < NN; t += blockDim.x) {
        int n = t >> 6, d = t & 63;
        const float* p = pts + (b * NP + n) * 3;
        float v1 = fmaf(p[0], WA[d], fmaf(p[1], WA[64 + d], fmaf(p[2], WA[128 + d], bA[d])));
        float v2 = fmaf(p[0], WB[d], fmaf(p[1], WB[64 + d], fmaf(p[2], WB[128 + d], bB[d])));
        S1t[d * 65 + n] = v1;
        S2s[n * 64 + d] = v2;
    }
    __syncthreads();
    const float cscale = 0.0625f;
    for (int e = threadIdx.x; e < NN; e += blockDim.x) {
        int r = e >> 6, c = e & 63;
        float acc = 0.f;
        #pragma unroll
        for (int d = 0; d < 64; d++)
            acc = fmaf(S1t[d * 65 + c], S2s[r * 64 + d], acc);
        g_att[(m * BSZ + b) * NN + e] = acc * cscale;
    }
}

// ---------------- k3b: analytic Sum_jkl det^2 per (b,i), exact f32 ----------------
__global__ void k3b_det2(const float* __restrict__ pts) {
    __shared__ float DX[64], DY[64], DZ[64];
    __shared__ float red2_s[2];
    int bx = blockIdx.x;
    int b = bx >> 6, i = bx & 63;
    int t = threadIdx.x, lane = t & 31, warp = t >> 5;
    const float* pi = pts + (b * 64 + i) * 3;
    const float* pt = pts + (b * 64 + t) * 3;
    float ax = pt[0] - pi[0], ay = pt[1] - pi[1], az = pt[2] - pi[2];
    DX[t] = ax; DY[t] = ay; DZ[t] = az;
    __syncthreads();
    float mxx = 0, mxy = 0, mxz = 0, myy = 0, myz = 0, mzz = 0;
    #pragma unroll 8
    for (int j = 0; j < 64; j++) {
        float x = DX[j], y = DY[j], z = DZ[j];
        mxx = fmaf(x, x, mxx); mxy = fmaf(x, y, mxy); mxz = fmaf(x, z, mxz);
        myy = fmaf(y, y, myy); myz = fmaf(y, z, myz); mzz = fmaf(z, z, mzz);
    }
    float q = 0.f;
    #pragma unroll 8
    for (int l = 0; l < 64; l++) {
        float lx = DX[l], ly = DY[l], lz = DZ[l];
        float vx = ay * lz - az * ly;
        float vy = az * lx - ax * lz;
        float vz = ax * ly - ay * lx;
        float f = mxx * vx * vx + myy * vy * vy + mzz * vz * vz
                + 2.f * (mxy * vx * vy + mxz * vx * vz + myz * vy * vz);
        q += f;
    }
    #pragma unroll
    for (int o = 16; o; o >>= 1) q += __shfl_down_sync(0xffffffffu, q, o);
    if (lane == 0) red2_s[warp] = q;
    __syncthreads();
    if (t == 0) g_det2[b * 64 + i] = red2_s[0] + red2_s[1];
}

// ---------------- pad: k3 must be the 4th launch (ncu capture slot) ----------------
__global__ void k_pad() {}

// ---------------- k3: 537M-eval tanh-gated det core, all-f16x2 math ----------------
// grid 4096 = B(32) x anchors(64) x k-halves(2); block 128 (4 warps).
// Warp owns 8 k's; per t4-iter each lane handles k_a and k_b=k_a+4,
// with the (l=lane, l+32) pair packed in the two f16 halves -> 4 evals/lane/j.
// Per-iter LDS: LDS.64 (jx,jy) + LDS.32 (jz) + LDS.64 (Ta,Tb) + LDS.32 (P)
// = 6 L1 wavefronts/iter (vs 7 in the LDS.128 variant — .w pad wasted a wf).
__global__ void __launch_bounds__(128, 8) k3_core(const float* __restrict__ pts) {
    __shared__ uint2    JXY_s[64];       // (jx2h, jy2h) LDS.64 bcast  512B
    __shared__ uint32_t JZ_s[64];        // jz2h LDS.32 bcast  256B
    __shared__ uint2    TT_s[16 * 64];   // [(w*4+t4)*64+j] = ((tka,tka),(tkb,tkb))  8KB
    __shared__ uint32_t P2_s[64 * 32];   // [j*32+lane] = f16x2(P(l,j), P(l+32,j))  8KB
    __shared__ float4   D4_s[64];        // raw f32 disp  1KB
    __shared__ float    red_s[4];

    int bx = blockIdx.x;
    int h  = bx & 1;
    int i  = (bx >> 1) & 63;
    int b  = bx >> 7;
    int k0 = h * 32;
    int tid = threadIdx.x, warp = tid >> 5, lane = tid & 31;

    const float* attq1 = g_att + (0 * BSZ + b) * NN;
    const float* attq2 = g_att + (1 * BSZ + b) * NN;
    const float* attq3 = g_att + (2 * BSZ + b) * NN;
    const float* Tjk   = g_att + (3 * BSZ + b) * NN;
    const float* Tjl   = g_att + (4 * BSZ + b) * NN;
    const float* Akl   = g_att + (5 * BSZ + b) * NN;

    // ---- prep ----
    {
        const float* pi = pts + (b * NP + i) * 3;
        float pix = pi[0], piy = pi[1], piz = pi[2];
        if (tid < 64) {
            const float* pp = pts + (b * NP + tid) * 3;
            float dx = pp[0] - pix, dy = pp[1] - piy, dz = pp[2] - piz;
            D4_s[tid] = make_float4(dx, dy, dz, 0.f);
            uint2 v;
            v.x = h22u(mkh2(dx, dx));
            v.y = h22u(mkh2(dy, dy));
            JXY_s[tid] = v;
            JZ_s[tid]  = h22u(mkh2(dz, dz));
        }
    }
    for (int idx = tid; idx < 1024; idx += 128) {       // paired pre-dup'd Tjk
        int w = idx >> 8, r = idx & 255;
        int t = r >> 6,   j = r & 63;
        int ka = k0 + 8 * w + t;
        float va = Tjk[ka * 64 + j];
        float vb = Tjk[(ka + 4) * 64 + j];
        uint2 tt;
        tt.x = h22u(mkh2(va, va));
        tt.y = h22u(mkh2(vb, vb));
        TT_s[idx] = tt;
    }
    for (int t = tid; t < 2048; t += 128) {             // fused P f16x2 pairs
        int lp = t & 31, j = t >> 5;
        float a1j = attq1[i * 64 + j];
        float lo = Tjl[lp * 64 + j]        + a1j + attq3[i * 64 + lp];
        float hi = Tjl[(lp + 32) * 64 + j] + a1j + attq3[i * 64 + lp + 32];
        P2_s[j * 32 + lp] = h22u(mkh2(lo, hi));
    }
    __syncthreads();

    // per-lane packed dl for (l=lane, l+32), pre-scaled by 1/16 (det scale)
    float4 da = D4_s[lane], db = D4_s[lane + 32];
    u64 sc = dup2(0.0625f);
    u64 dlx2 = mul2(pk2(da.x, db.x), sc);
    u64 dly2 = mul2(pk2(da.y, db.y), sc);
    u64 dlz2 = mul2(pk2(da.z, db.z), sc);
    float accA = 0.f, accB = 0.f;

    #pragma unroll 1
    for (int t4 = 0; t4 < 4; t4++) {
        int ka = k0 + 8 * warp + t4;             // uniform within warp
        int kb = ka + 4;
        float4 dka = D4_s[ka];
        float4 dkb = D4_s[kb];
        float aika = __ldg(attq2 + i * 64 + ka);
        float aikb = __ldg(attq2 + i * 64 + kb);
        __half2 base_ha = mkh2(aika + __ldg(Akl + ka * 64 + lane),
                               aika + __ldg(Akl + ka * 64 + lane + 32));
        __half2 base_hb = mkh2(aikb + __ldg(Akl + kb * 64 + lane),
                               aikb + __ldg(Akl + kb * 64 + lane + 32));
        // cross(dk, dl/16) in f32x2, then pack to f16x2 (hoisted)
        __half2 cxa = h2_from_f32x2(fma2(dup2(dka.y), dlz2, mul2(dup2(-dka.z), dly2)));
        __half2 cya = h2_from_f32x2(fma2(dup2(dka.z), dlx2, mul2(dup2(-dka.x), dlz2)));
        __half2 cza = h2_from_f32x2(fma2(dup2(dka.x), dly2, mul2(dup2(-dka.y), dlx2)));
        __half2 cxb = h2_from_f32x2(fma2(dup2(dkb.y), dlz2, mul2(dup2(-dkb.z), dly2)));
        __half2 cyb = h2_from_f32x2(fma2(dup2(dkb.z), dlx2, mul2(dup2(-dkb.x), dlz2)));
        __half2 czb = h2_from_f32x2(fma2(dup2(dkb.x), dly2, mul2(dup2(-dkb.y), dlx2)));
        const uint2* TRow = TT_s + (warp * 4 + t4) * 64;

        #pragma unroll 1
        for (int j8 = 0; j8 < 8; j8++) {        // 8-j f16 windows (R13-proven)
            __half2 winA = u2h2(0u), winB = u2h2(0u);
            #pragma unroll
            for (int jj = 0; jj < 8; jj++) {
                int j = j8 * 8 + jj;
                uint2 jv = JXY_s[j];                         // LDS.64 bcast (2 wf)
                __half2 jx = u2h2(jv.x), jy = u2h2(jv.y);
                __half2 jz = u2h2(JZ_s[j]);                  // LDS.32 bcast (1 wf)
                uint2 tt = TRow[j];                          // LDS.64 bcast (2 wf)
                __half2 ta = u2h2(tt.x), tb = u2h2(tt.y);
                __half2 p  = u2h2(P2_s[j * 32 + lane]);      // LDS.32 per-lane (1 wf)
                __half2 ea = __hadd2(__hadd2(p, ta), base_ha);
                __half2 eb = __hadd2(__hadd2(p, tb), base_hb);
                __half2 tha = tanh_h2(ea);                   // 1 XU per 2 evals
                __half2 thb = tanh_h2(eb);
                __half2 deta = __hfma2(jx, cxa, __hfma2(jy, cya, __hmul2(jz, cza)));
                __half2 detb = __hfma2(jx, cxb, __hfma2(jy, cyb, __hmul2(jz, czb)));
                winA = __hfma2(__hmul2(deta, deta), tha, winA);
                winB = __hfma2(__hmul2(detb, detb), thb, winB);
            }
            float l0, h0, l1, h1;
            widen_h2(h22u(winA), l0, h0);                    // ALU-only widen
            widen_h2(h22u(winB), l1, h1);
            accA += (l0 + h0);
            accB += (l1 + h1);
        }
    }

    // ---- reduction ----
    float acc = (accA + accB) * 256.f;          // undo det/16 scaling
    #pragma unroll
    for (int o = 16; o; o >>= 1) acc += __shfl_down_sync(0xffffffffu, acc, o);
    if (lane == 0) red_s[warp] = acc;
    __syncthreads();
    if (tid == 0) {
        float s = red_s[0] + red_s[1] + red_s[2] + red_s[3];
        g_anchor2[h * BSZ * NP + b * NP + i] = s;
    }
}

// ---------------- k4: pooled -> gelu MLP head (warp per batch) ----------------
// anchor_i = 0.5*(Sum det^2 + Sum tanh*det^2); pooled = Sum_i anchor_i / N^4
__global__ void k4_head(const float* __restrict__ W1, const float* __restrict__ b1,
                        const float* __restrict__ W2, const float* __restrict__ b2,
                        float* __restrict__ out) {
    int warp = threadIdx.x >> 5, lane = threadIdx.x & 31;
    int b = warp;
    float s = g_anchor2[b * 64 + lane] + g_anchor2[b * 64 + lane + 32]
            + g_anchor2[BSZ * NP + b * 64 + lane] + g_anchor2[BSZ * NP + b * 64 + lane + 32]
            + g_det2[b * 64 + lane] + g_det2[b * 64 + lane + 32];
    #pragma unroll
    for (int o = 16; o; o >>= 1) s += __shfl_xor_sync(0xffffffffu, s, o);
    float pooled = s * (0.5f / 16777216.f);        // 0.5 gate split, / (N^3 * N)
    float x  = fmaf(pooled, W1[lane], b1[lane]);   // lane = hidden unit
    float x3 = x * x * x;
    float t  = tanhf(0.7978845608028654f * fmaf(0.044715f, x3, x));
    float hc = 0.5f * x * (1.f + t);               // tanh-approx gelu
    float y  = hc * W2[lane];
    #pragma unroll
    for (int o = 16; o; o >>= 1) y += __shfl_xor_sync(0xffffffffu, y, o);
    if (lane == 0) out[b] = y + b2[0];
}

// ---------------- launch ----------------
extern "C" void kernel_launch(void* const* d_in, const int* in_sizes, int n_in,
                              void* d_out, int out_size) {
    const float* pts = (const float*)d_in[0];
    const float* Wq  = (const float*)d_in[1];
    const float* bq  = (const float*)d_in[2];
    const float* Wk1 = (const float*)d_in[3];
    const float* bk1 = (const float*)d_in[4];
    const float* Wk2 = (const float*)d_in[5];
    const float* bk2 = (const float*)d_in[6];
    const float* Wk3 = (const float*)d_in[7];
    const float* bk3 = (const float*)d_in[8];
    const float* W1  = (const float*)d_in[9];
    const float* b1  = (const float*)d_in[10];
    const float* W2  = (const float*)d_in[11];
    const float* b2  = (const float*)d_in[12];
    float* out = (float*)d_out;

    k12_att<<<BSZ * 6, 256>>>(pts, Wq, bq, Wk1, bk1, Wk2, bk2, Wk3, bk3);
    k3b_det2<<<BSZ * NP, 64>>>(pts);
    k_pad<<<1, 32>>>();                       // k3 = 4th launch -> ncu capture slot
    k3_core<<<BSZ * NP * 2, 128>>>(pts);
    k4_head<<<1, BSZ * 32>>>(W1, b1, W2, b2, out);
}